// round 2
// baseline (speedup 1.0000x reference)
#include <cuda_runtime.h>
#include <stdint.h>

#define HH 1024
#define WW 1024
#define BB 8
#define CC 3
#define HW (HH*WW)
#define SPITCH 1040
#define SEG 16
#define SEGROWS 64

// scratch (__device__ globals; no allocation allowed)
__device__ float4 g_packed[(size_t)BB*HW];          // (r,g,b,1)  128 MB
__device__ float  g_cnt[2u*BB*HW];                  // 64 MB
__device__ float  g_segsum[16*SEG*4*WW];            // 16 MB

// ---------- float4 helpers ----------
__device__ __forceinline__ float4 z4() { return make_float4(0,0,0,0); }
__device__ __forceinline__ float4 f4add(float4 a, float4 b){
    return make_float4(a.x+b.x, a.y+b.y, a.z+b.z, a.w+b.w);
}
__device__ __forceinline__ void f4fma(float4& a, float s, float4 p){
    a.x = fmaf(s, p.x, a.x); a.y = fmaf(s, p.y, a.y);
    a.z = fmaf(s, p.z, a.z); a.w = fmaf(s, p.w, a.w);
}

__device__ __forceinline__ void padd(float4& a, float s,
                                     const float4* __restrict__ pb,
                                     int row, int col) {
    float4 p = __ldg(pb + (size_t)row*WW + col);
    f4fma(a, s, p);
}

__device__ __forceinline__ float4 warp_iscan4(float4 v) {
    int lane = threadIdx.x & 31;
    #pragma unroll
    for (int o = 1; o < 32; o <<= 1) {
        float ax = __shfl_up_sync(0xffffffffu, v.x, o);
        float ay = __shfl_up_sync(0xffffffffu, v.y, o);
        float az = __shfl_up_sync(0xffffffffu, v.z, o);
        float aw = __shfl_up_sync(0xffffffffu, v.w, o);
        if (lane >= o) { v.x += ax; v.y += ay; v.z += az; v.w += aw; }
    }
    return v;
}

// ---------- K0: pack channels (r,g,b,1) ----------
__global__ __launch_bounds__(256)
void k_pack(const float* __restrict__ image) {
    const size_t i = (size_t)blockIdx.x*1024 + threadIdx.x*4;   // pixel idx in b*HW
    const size_t b = i / HW;
    const size_t o = i - b*HW;
    const float* p = image + b*CC*HW + o;
    float4 r = __ldg((const float4*)(p));
    float4 g = __ldg((const float4*)(p + HW));
    float4 bl= __ldg((const float4*)(p + 2*HW));
    float4* dst = g_packed + i;
    dst[0] = make_float4(r.x, g.x, bl.x, 1.f);
    dst[1] = make_float4(r.y, g.y, bl.y, 1.f);
    dst[2] = make_float4(r.z, g.z, bl.z, 1.f);
    dst[3] = make_float4(r.w, g.w, bl.w, 1.f);
}

// ---------- generic border delta (exact port of proven round-1 path) ----------
__device__ void generic_delta(int y, int x, const uint8_t sR[16][SPITCH],
                              const float4* __restrict__ pb,
                              float4& dl, float4& dr) {
    for (int r = 0; r < 8; ++r) {
        const int t0 = (y > 0) ? y + r : 0;
        const int t1 = (y > 0) ? y + r : r;
        const int brow = y - r - 1;
        const int a0 = (x > 0) ? x + 2*r : 0;
        const int a1 = (x > 0) ? x + 2*r : 2*r;
        const int xB = x - 1;
        const int xD = x - 2*r - 1;
        for (int yy = t0; yy <= t1; ++yy) {
            const int idx = yy - y + 8;
            for (int a = a0; a <= a1; ++a)
                if (a < WW && sR[idx][a] == r) padd(dl,  1.f, pb, yy, a);
            if (xB >= 0 && sR[idx][xB] == r)   padd(dl, -1.f, pb, yy, xB);
            if (sR[idx][x] == r)               padd(dr,  1.f, pb, yy, x);
            if (xD >= 0 && sR[idx][xD] == r)   padd(dr, -1.f, pb, yy, xD);
        }
        if (brow >= 0) {
            const int idx = 7 - r;
            for (int a = a0; a <= a1; ++a)
                if (a < WW && sR[idx][a] == r) padd(dl, -1.f, pb, brow, a);
            if (xB >= 0 && sR[idx][xB] == r)   padd(dl,  1.f, pb, brow, xB);
            if (sR[idx][x] == r)               padd(dr, -1.f, pb, brow, x);
            if (xD >= 0 && sR[idx][xD] == r)   padd(dr,  1.f, pb, brow, xD);
        }
    }
}

// ---------- K1: mask-build + gather + row (x) inclusive scan ----------
__global__ __launch_bounds__(256)
void k_rowscan(const float* __restrict__ depth, float* __restrict__ out) {
    __shared__ uint8_t  sR[16][SPITCH];
    __shared__ uint32_t mw0[1056];     // classes 0..3 (top rows), byte c = class, bit r
    __shared__ uint32_t mw1[1056];     // classes 4..7 (bottom rows)
    __shared__ float4 wtl[9], wtr[9];  // [8]=block sum

    const int y   = blockIdx.x;
    const int b   = blockIdx.y;
    const int tid = threadIdx.x;
    const int lane = tid & 31, wid = tid >> 5;

    // zero masks
    for (int i = tid; i < 1056; i += 256) { mw0[i] = 0u; mw1[i] = 0u; }
    __syncthreads();

    // fill R window rows [y-8, y+7]; build corner masks from registers
    const float* drow = depth + (size_t)b*HW;
    for (int i = tid; i < 16*SPITCH; i += 256) {
        const int rr  = i / SPITCH;
        const int col = i - rr*SPITCH;
        const int ar  = y - 8 + rr;
        int v = 255;
        if (col < WW && ar >= 0 && ar < HH)
            v = (int)__ldg(drow + (size_t)ar*WW + col);     // floor; depth in [0,8)
        sR[rr][col] = (uint8_t)v;
        if (v < 8) {
            if (rr == 8 + v) {               // top-row source, r=v
                const int r = v;
                atomicOr(&mw0[col - 2*r + 16], 1u << r);          // cls0 L+ @ u-2r
                atomicOr(&mw0[col + 1   + 16], 1u << (8 + r));    // cls1 L- @ u+1
                atomicOr(&mw0[col       + 16], 1u << (16 + r));   // cls2 R+ @ u
                atomicOr(&mw0[col + 2*r + 17], 1u << (24 + r));   // cls3 R- @ u+2r+1
            } else if (rr == 7 - v) {        // bottom-row source, r=v
                const int r = v;
                atomicOr(&mw1[col - 2*r + 16], 1u << r);          // cls4 L- @ u-2r
                atomicOr(&mw1[col + 1   + 16], 1u << (8 + r));    // cls5 L+ @ u+1
                atomicOr(&mw1[col       + 16], 1u << (16 + r));   // cls6 R- @ u
                atomicOr(&mw1[col + 2*r + 17], 1u << (24 + r));   // cls7 R+ @ u+2r+1
            }
        }
    }
    __syncthreads();

    const float4* pb = g_packed + (size_t)b*HW;
    float4 carL = z4(), carR = z4();

    const int vbL = b, vbR = BB + b;
    float* cL = g_cnt + (size_t)vbL*HW + (size_t)y*WW;
    float* cRp= g_cnt + (size_t)vbR*HW + (size_t)y*WW;
    float* oL = out + (size_t)vbL*CC*HW + (size_t)y*WW;
    float* oR = out + (size_t)vbR*CC*HW + (size_t)y*WW;

    #pragma unroll 1
    for (int seg = 0; seg < 4; ++seg) {
        const int x = tid + 256*seg;
        float4 dl = z4(), dr = z4();

        if (y > 0 && x > 0) {
            uint64_t m = (uint64_t)mw0[x + 16] | ((uint64_t)mw1[x + 16] << 32);
            while (m) {
                const int i = __ffsll((long long)m) - 1;
                m &= m - 1;
                const int r   = i & 7;
                const int cls = i >> 3;
                const int row = (cls < 4) ? (y + r) : (y - r - 1);
                const int c3  = cls & 3;
                const int col = (c3 == 0) ? x + 2*r :
                                (c3 == 1) ? x - 1   :
                                (c3 == 2) ? x       : x - 2*r - 1;
                const float4 p = __ldg(pb + (size_t)row*WW + col);
                const float s = ((0x5Au >> cls) & 1u) ? -1.f : 1.f;
                if ((0x33u >> cls) & 1u) f4fma(dl, s, p);
                else                     f4fma(dr, s, p);
            }
        } else {
            generic_delta(y, x, sR, pb, dl, dr);
        }

        // block inclusive scan of this 256-wide segment
        float4 il = warp_iscan4(dl);
        float4 ir = warp_iscan4(dr);
        if (lane == 31) { wtl[wid] = il; wtr[wid] = ir; }
        __syncthreads();
        if (tid == 0) {
            float4 s = z4();
            #pragma unroll
            for (int w = 0; w < 8; ++w) { float4 t = wtl[w]; wtl[w] = s; s = f4add(s, t); }
            wtl[8] = s;
            s = z4();
            #pragma unroll
            for (int w = 0; w < 8; ++w) { float4 t = wtr[w]; wtr[w] = s; s = f4add(s, t); }
            wtr[8] = s;
        }
        __syncthreads();
        const float4 tl = f4add(carL, f4add(wtl[wid], il));
        const float4 tr = f4add(carR, f4add(wtr[wid], ir));

        // stores (coalesced: lane stride 1)
        cL [x]        = tl.w;
        cRp[x]        = tr.w;
        oL [x]        = tl.x;
        oL [x +   HW] = tl.y;
        oL [x + 2*HW] = tl.z;
        oR [x]        = tr.x;
        oR [x +   HW] = tr.y;
        oR [x + 2*HW] = tr.z;

        carL = f4add(carL, wtl[8]);
        carR = f4add(carR, wtr[8]);
        __syncthreads();
    }
}

// ---------- K2a: per-segment column sums (plane-split) ----------
__global__ __launch_bounds__(256)
void k_colsum(const float* __restrict__ out) {
    const int plane = blockIdx.x;                    // 0=cnt, 1..3=channels
    const int seg   = blockIdx.y;                    // 0..15
    const int vb    = blockIdx.z;                    // 0..15
    const int xc    = threadIdx.x * 4;

    const float* src = (plane == 0)
        ? g_cnt + (size_t)vb*HW
        : out + ((size_t)vb*CC + (plane-1))*HW;

    float4 s = z4();
    const int y0 = seg * SEGROWS;
    #pragma unroll 8
    for (int yy = 0; yy < SEGROWS; ++yy)
        s = f4add(s, __ldg((const float4*)(src + (size_t)(y0 + yy)*WW + xc)));

    *(float4*)(g_segsum + (size_t)(((vb*SEG + seg)*4 + plane))*WW + xc) = s;
}

// ---------- K2b: column scan (seeded) + finalize ----------
__global__ __launch_bounds__(256)
void k_colscan_final(float* __restrict__ out) {
    const int seg = blockIdx.y;
    const int vb  = blockIdx.z;
    const int xc  = threadIdx.x * 4;

    float4 r0 = z4(), r1 = z4(), r2 = z4(), r3 = z4();
    for (int s = 0; s < seg; ++s) {
        const float* ss = g_segsum + (size_t)((vb*SEG + s)*4)*WW + xc;
        r0 = f4add(r0, __ldg((const float4*)(ss + 0*WW)));
        r1 = f4add(r1, __ldg((const float4*)(ss + 1*WW)));
        r2 = f4add(r2, __ldg((const float4*)(ss + 2*WW)));
        r3 = f4add(r3, __ldg((const float4*)(ss + 3*WW)));
    }

    const float* p0 = g_cnt + (size_t)vb*HW + xc;
    float* p1 = out + ((size_t)vb*CC + 0)*HW + xc;
    float* p2 = p1 + HW;
    float* p3 = p1 + 2*HW;

    const int y0 = seg * SEGROWS;
    #pragma unroll 2
    for (int yy = 0; yy < SEGROWS; ++yy) {
        const size_t o = (size_t)(y0 + yy)*WW;
        r0 = f4add(r0, __ldg((const float4*)(p0 + o)));
        r1 = f4add(r1, __ldg((const float4*)(p1 + o)));
        r2 = f4add(r2, __ldg((const float4*)(p2 + o)));
        r3 = f4add(r3, __ldg((const float4*)(p3 + o)));

        float4 inv;
        inv.x = __fdividef(1.0f, fmaxf(r0.x, 1.0f));
        inv.y = __fdividef(1.0f, fmaxf(r0.y, 1.0f));
        inv.z = __fdividef(1.0f, fmaxf(r0.z, 1.0f));
        inv.w = __fdividef(1.0f, fmaxf(r0.w, 1.0f));

        *(float4*)(p1 + o) = make_float4(__saturatef(r1.x*inv.x), __saturatef(r1.y*inv.y),
                                         __saturatef(r1.z*inv.z), __saturatef(r1.w*inv.w));
        *(float4*)(p2 + o) = make_float4(__saturatef(r2.x*inv.x), __saturatef(r2.y*inv.y),
                                         __saturatef(r2.z*inv.z), __saturatef(r2.w*inv.w));
        *(float4*)(p3 + o) = make_float4(__saturatef(r3.x*inv.x), __saturatef(r3.y*inv.y),
                                         __saturatef(r3.z*inv.z), __saturatef(r3.w*inv.w));
    }
}

extern "C" void kernel_launch(void* const* d_in, const int* in_sizes, int n_in,
                              void* d_out, int out_size) {
    const float* image = (const float*)d_in[0];   // (8,3,1024,1024) f32
    const float* depth = (const float*)d_in[1];   // (8,1024,1024)   f32
    float* out = (float*)d_out;                   // [left(8,3,H,W), right(8,3,H,W)]

    k_pack<<<BB*HW/1024, 256>>>(image);
    k_rowscan<<<dim3(HH, BB), 256>>>(depth, out);
    k_colsum<<<dim3(4, SEG, 16), 256>>>(out);
    k_colscan_final<<<dim3(1, SEG, 16), 256>>>(out);
}

// round 3
// speedup vs baseline: 1.1514x; 1.1514x over previous
#include <cuda_runtime.h>
#include <stdint.h>

#define HH 1024
#define WW 1024
#define BB 8
#define CC 3
#define HW (HH*WW)
#define SPITCH 1040   // 1024 + 16 right pad (255-filled), divisible by 4
#define SEG 32
#define SEGROWS 32

// scratch (__device__ globals; no allocation allowed)
__device__ float4  g_packed[(size_t)BB*HW];         // (r,g,b,1)  128 MB
__device__ uint8_t g_R[(size_t)BB*HW];              // floor(depth) 8 MB
__device__ float   g_cnt[2u*BB*HW];                 // 64 MB
__device__ float   g_segsum[16*SEG*4*WW];           // 8 MB

// ---------- float4 helpers ----------
__device__ __forceinline__ float4 z4() { return make_float4(0,0,0,0); }
__device__ __forceinline__ float4 f4add(float4 a, float4 b){
    return make_float4(a.x+b.x, a.y+b.y, a.z+b.z, a.w+b.w);
}
__device__ __forceinline__ float4 f4sub(float4 a, float4 b){
    return make_float4(a.x-b.x, a.y-b.y, a.z-b.z, a.w-b.w);
}
__device__ __forceinline__ void f4fma(float4& a, float s, float4 p){
    a.x = fmaf(s, p.x, a.x); a.y = fmaf(s, p.y, a.y);
    a.z = fmaf(s, p.z, a.z); a.w = fmaf(s, p.w, a.w);
}
__device__ __forceinline__ void padd(float4& a, float s,
                                     const float4* __restrict__ pb,
                                     int row, int col) {
    float4 p = __ldg(pb + (size_t)row*WW + col);
    f4fma(a, s, p);
}

__device__ __forceinline__ float4 warp_iscan4(float4 v) {
    int lane = threadIdx.x & 31;
    #pragma unroll
    for (int o = 1; o < 32; o <<= 1) {
        float ax = __shfl_up_sync(0xffffffffu, v.x, o);
        float ay = __shfl_up_sync(0xffffffffu, v.y, o);
        float az = __shfl_up_sync(0xffffffffu, v.z, o);
        float aw = __shfl_up_sync(0xffffffffu, v.w, o);
        if (lane >= o) { v.x += ax; v.y += ay; v.z += az; v.w += aw; }
    }
    return v;
}

// ---------- K0a: pack channels (r,g,b,1) ----------
__global__ __launch_bounds__(256)
void k_pack(const float* __restrict__ image) {
    const size_t i = (size_t)blockIdx.x*1024 + threadIdx.x*4;
    const size_t b = i / HW;
    const size_t o = i - b*HW;
    const float* p = image + b*CC*HW + o;
    float4 r = __ldg((const float4*)(p));
    float4 g = __ldg((const float4*)(p + HW));
    float4 bl= __ldg((const float4*)(p + 2*HW));
    float4* dst = g_packed + i;
    dst[0] = make_float4(r.x, g.x, bl.x, 1.f);
    dst[1] = make_float4(r.y, g.y, bl.y, 1.f);
    dst[2] = make_float4(r.z, g.z, bl.z, 1.f);
    dst[3] = make_float4(r.w, g.w, bl.w, 1.f);
}

// ---------- K0b: depth -> uint8 radius ----------
__global__ __launch_bounds__(256)
void k_r8(const float* __restrict__ depth) {
    const size_t i = (size_t)blockIdx.x*1024 + threadIdx.x*4;
    float4 d = __ldg((const float4*)(depth + i));
    uchar4 v;
    v.x = (uint8_t)(int)d.x; v.y = (uint8_t)(int)d.y;
    v.z = (uint8_t)(int)d.z; v.w = (uint8_t)(int)d.w;
    *(uchar4*)(g_R + i) = v;
}

// ---------- generic border delta (proven round-1 path, packed gather) ----------
__device__ void generic_delta(int y, int x, const uint8_t sR[16][SPITCH],
                              const float4* __restrict__ pb,
                              float4& dl, float4& dr) {
    for (int r = 0; r < 8; ++r) {
        const int t0 = (y > 0) ? y + r : 0;
        const int t1 = (y > 0) ? y + r : r;
        const int brow = y - r - 1;
        const int a0 = (x > 0) ? x + 2*r : 0;
        const int a1 = (x > 0) ? x + 2*r : 2*r;
        const int xB = x - 1;
        const int xD = x - 2*r - 1;
        for (int yy = t0; yy <= t1; ++yy) {
            const int idx = yy - y + 8;
            for (int a = a0; a <= a1; ++a)
                if (a < WW && sR[idx][a] == r) padd(dl,  1.f, pb, yy, a);
            if (xB >= 0 && sR[idx][xB] == r)   padd(dl, -1.f, pb, yy, xB);
            if (sR[idx][x] == r)               padd(dr,  1.f, pb, yy, x);
            if (xD >= 0 && sR[idx][xD] == r)   padd(dr, -1.f, pb, yy, xD);
        }
        if (brow >= 0) {
            const int idx = 7 - r;
            for (int a = a0; a <= a1; ++a)
                if (a < WW && sR[idx][a] == r) padd(dl, -1.f, pb, brow, a);
            if (xB >= 0 && sR[idx][xB] == r)   padd(dl,  1.f, pb, brow, xB);
            if (sR[idx][x] == r)               padd(dr, -1.f, pb, brow, x);
            if (xD >= 0 && sR[idx][xD] == r)   padd(dr,  1.f, pb, brow, xD);
        }
    }
}

// ---------- K1: delta gather + row (x) inclusive scan ----------
__global__ __launch_bounds__(256)
void k_rowscan(float* __restrict__ out) {
    __shared__ uint8_t sR[16][SPITCH];
    __shared__ float4 wtl[8], wtr[8];

    const int y   = blockIdx.x;
    const int b   = blockIdx.y;
    const int tid = threadIdx.x;

    // fill R window rows [y-8, y+7] from u8 plane; OOB -> 255. uchar4 vectorized.
    const uint8_t* rb = g_R + (size_t)b*HW;
    for (int i = tid; i < 16*(SPITCH/4); i += 256) {
        const int rr = i / (SPITCH/4);
        const int c4 = (i - rr*(SPITCH/4)) * 4;
        const int ar = y - 8 + rr;
        uchar4 v = make_uchar4(255,255,255,255);
        if (c4 + 3 < WW && ar >= 0 && ar < HH)
            v = __ldg((const uchar4*)(rb + (size_t)ar*WW + c4));
        *(uchar4*)&sR[rr][c4] = v;
    }
    __syncthreads();

    const float4* pb = g_packed + (size_t)b*HW;

    float4 pl[4], pr[4];
    float4 accl = z4(), accr = z4();

    for (int i = 0; i < 4; ++i) {
        const int x = 4*tid + i;
        float4 dl = z4(), dr = z4();

        if (y > 0 && x > 0) {
            // ---- fast interior path: 8 independent predicated LDG.128 per r ----
            #pragma unroll
            for (int r = 0; r < 8; ++r) {
                const int ti = 8 + r, bi = 7 - r;
                const int trow = y + r, brow = y - r - 1;
                const int xA = x + 2*r;          // padded smem: safe to 1039
                const int xB = x - 1;
                const int xD = x - 2*r - 1;
                if (sR[ti][xA] == r) padd(dl,  1.f, pb, trow, xA);
                if (sR[ti][xB] == r) padd(dl, -1.f, pb, trow, xB);
                if (sR[bi][xA] == r) padd(dl, -1.f, pb, brow, xA);
                if (sR[bi][xB] == r) padd(dl,  1.f, pb, brow, xB);
                if (sR[ti][x]  == r) padd(dr,  1.f, pb, trow, x);
                if (sR[bi][x]  == r) padd(dr, -1.f, pb, brow, x);
                if (xD >= 0) {
                    if (sR[ti][xD] == r) padd(dr, -1.f, pb, trow, xD);
                    if (sR[bi][xD] == r) padd(dr,  1.f, pb, brow, xD);
                }
            }
        } else {
            generic_delta(y, x, sR, pb, dl, dr);
        }
        accl = f4add(accl, dl);  pl[i] = accl;
        accr = f4add(accr, dr);  pr[i] = accr;
    }

    // ---- block-wide inclusive scan along x ----
    const int lane = tid & 31, wid = tid >> 5;
    float4 tl = pl[3], tr = pr[3];
    float4 il = warp_iscan4(tl);
    float4 ir = warp_iscan4(tr);
    if (lane == 31) { wtl[wid] = il; wtr[wid] = ir; }
    __syncthreads();
    if (tid == 0) {
        float4 s = z4();
        #pragma unroll
        for (int w = 0; w < 8; ++w) { float4 t = wtl[w]; wtl[w] = s; s = f4add(s, t); }
        s = z4();
        #pragma unroll
        for (int w = 0; w < 8; ++w) { float4 t = wtr[w]; wtr[w] = s; s = f4add(s, t); }
    }
    __syncthreads();
    float4 offl = f4add(wtl[wid], f4sub(il, tl));
    float4 offr = f4add(wtr[wid], f4sub(ir, tr));

    float4 rl[4], rr[4];
    #pragma unroll
    for (int i = 0; i < 4; ++i) { rl[i] = f4add(pl[i], offl); rr[i] = f4add(pr[i], offr); }

    // ---- stores: cnt (.w) -> g_cnt, channels (.x,.y,.z) -> d_out planes ----
    const int vbL = b, vbR = BB + b;
    const size_t rowoff = (size_t)y*WW + 4*tid;

    *(float4*)(g_cnt + (size_t)vbL*HW + rowoff) =
        make_float4(rl[0].w, rl[1].w, rl[2].w, rl[3].w);
    *(float4*)(g_cnt + (size_t)vbR*HW + rowoff) =
        make_float4(rr[0].w, rr[1].w, rr[2].w, rr[3].w);

    float* oL = out + (size_t)vbL*CC*HW + rowoff;
    float* oR = out + (size_t)vbR*CC*HW + rowoff;
    *(float4*)(oL)        = make_float4(rl[0].x, rl[1].x, rl[2].x, rl[3].x);
    *(float4*)(oL + HW)   = make_float4(rl[0].y, rl[1].y, rl[2].y, rl[3].y);
    *(float4*)(oL + 2*HW) = make_float4(rl[0].z, rl[1].z, rl[2].z, rl[3].z);
    *(float4*)(oR)        = make_float4(rr[0].x, rr[1].x, rr[2].x, rr[3].x);
    *(float4*)(oR + HW)   = make_float4(rr[0].y, rr[1].y, rr[2].y, rr[3].y);
    *(float4*)(oR + 2*HW) = make_float4(rr[0].z, rr[1].z, rr[2].z, rr[3].z);
}

// ---------- K2a: per-segment column sums (plane-split) ----------
__global__ __launch_bounds__(256)
void k_colsum(const float* __restrict__ out) {
    const int plane = blockIdx.x;                    // 0=cnt, 1..3=channels
    const int seg   = blockIdx.y;                    // 0..SEG-1
    const int vb    = blockIdx.z;                    // 0..15
    const int xc    = threadIdx.x * 4;

    const float* src = (plane == 0)
        ? g_cnt + (size_t)vb*HW
        : out + ((size_t)vb*CC + (plane-1))*HW;

    float4 s = z4();
    const int y0 = seg * SEGROWS;
    #pragma unroll 8
    for (int yy = 0; yy < SEGROWS; ++yy)
        s = f4add(s, __ldg((const float4*)(src + (size_t)(y0 + yy)*WW + xc)));

    *(float4*)(g_segsum + (size_t)(((vb*SEG + seg)*4 + plane))*WW + xc) = s;
}

// ---------- K2b: column scan (seeded) + finalize ----------
__global__ __launch_bounds__(256)
void k_colscan_final(float* __restrict__ out) {
    const int seg = blockIdx.y;
    const int vb  = blockIdx.z;
    const int xc  = threadIdx.x * 4;

    float4 r0 = z4(), r1 = z4(), r2 = z4(), r3 = z4();
    for (int s = 0; s < seg; ++s) {
        const float* ss = g_segsum + (size_t)((vb*SEG + s)*4)*WW + xc;
        r0 = f4add(r0, __ldg((const float4*)(ss + 0*WW)));
        r1 = f4add(r1, __ldg((const float4*)(ss + 1*WW)));
        r2 = f4add(r2, __ldg((const float4*)(ss + 2*WW)));
        r3 = f4add(r3, __ldg((const float4*)(ss + 3*WW)));
    }

    const float* p0 = g_cnt + (size_t)vb*HW + xc;
    float* p1 = out + ((size_t)vb*CC + 0)*HW + xc;
    float* p2 = p1 + HW;
    float* p3 = p1 + 2*HW;

    const int y0 = seg * SEGROWS;
    #pragma unroll 2
    for (int yy = 0; yy < SEGROWS; ++yy) {
        const size_t o = (size_t)(y0 + yy)*WW;
        r0 = f4add(r0, __ldg((const float4*)(p0 + o)));
        r1 = f4add(r1, __ldg((const float4*)(p1 + o)));
        r2 = f4add(r2, __ldg((const float4*)(p2 + o)));
        r3 = f4add(r3, __ldg((const float4*)(p3 + o)));

        float4 inv;
        inv.x = __fdividef(1.0f, fmaxf(r0.x, 1.0f));
        inv.y = __fdividef(1.0f, fmaxf(r0.y, 1.0f));
        inv.z = __fdividef(1.0f, fmaxf(r0.z, 1.0f));
        inv.w = __fdividef(1.0f, fmaxf(r0.w, 1.0f));

        *(float4*)(p1 + o) = make_float4(__saturatef(r1.x*inv.x), __saturatef(r1.y*inv.y),
                                         __saturatef(r1.z*inv.z), __saturatef(r1.w*inv.w));
        *(float4*)(p2 + o) = make_float4(__saturatef(r2.x*inv.x), __saturatef(r2.y*inv.y),
                                         __saturatef(r2.z*inv.z), __saturatef(r2.w*inv.w));
        *(float4*)(p3 + o) = make_float4(__saturatef(r3.x*inv.x), __saturatef(r3.y*inv.y),
                                         __saturatef(r3.z*inv.z), __saturatef(r3.w*inv.w));
    }
}

extern "C" void kernel_launch(void* const* d_in, const int* in_sizes, int n_in,
                              void* d_out, int out_size) {
    const float* image = (const float*)d_in[0];   // (8,3,1024,1024) f32
    const float* depth = (const float*)d_in[1];   // (8,1024,1024)   f32
    float* out = (float*)d_out;                   // [left(8,3,H,W), right(8,3,H,W)]

    k_pack<<<BB*HW/1024, 256>>>(image);
    k_r8  <<<BB*HW/1024, 256>>>(depth);
    k_rowscan<<<dim3(HH, BB), 256>>>(out);
    k_colsum<<<dim3(4, SEG, 16), 256>>>(out);
    k_colscan_final<<<dim3(1, SEG, 16), 256>>>(out);
}